// round 11
// baseline (speedup 1.0000x reference)
#include <cuda_runtime.h>
#include <cstdint>

// x (256,18,18,512) f32, W (18,512,512) f32, b (18,512) f32, idx (18) i32
#define KB_   256
#define O_    18
#define J_    18
#define DIM   512
#define M_TOTAL (KB_ * J_)        // 4608
#define BM    128
#define BN    128
#define BK    32
#define ST    36                  // smem row stride (u32): BK + 4 pad (conflict-free LDSM/STS)
#define NKT   (DIM / BK)          // 16
#define STAGES 3
#define NTHREADS 256
#define SCALE_F 0.044194173824159216f

#define SA_U32 (BM * ST)                    // 4608
#define SB_U32 (BN * ST)                    // 4608
#define STG_U32 (SA_U32 + SB_U32)           // 9216 u32 = 36864 B
#define SMEM_BYTES (STAGES * STG_U32 * 4)   // 110592

__device__ int g_sel[J_];
__device__ float g_Wt[O_ * DIM * DIM];      // W pre-converted to tf32 bit patterns

__device__ __forceinline__ uint32_t f2tf32(float f) {
    uint32_t u;
    asm("cvt.rna.tf32.f32 %0, %1;" : "=r"(u) : "f"(f));
    return u;
}

// merged prep: block 0 builds g_sel; all blocks convert W -> tf32 bits
__global__ void prep_kernel(const float* __restrict__ W, const int* __restrict__ idx, int n) {
    if (blockIdx.x == 0 && threadIdx.x < 32) {
        int t = threadIdx.x;
        if (t < J_) g_sel[t] = 0;
        __syncwarp();
        if (t < n) {
            int v = idx[t];
            if (v >= 0 && v < J_) g_sel[v] = 1;
        }
    }
    const int total4 = O_ * DIM * DIM / 4;
    for (int i = blockIdx.x * blockDim.x + threadIdx.x; i < total4;
         i += gridDim.x * blockDim.x) {
        float4 v = reinterpret_cast<const float4*>(W)[i];
        uint4 u = make_uint4(f2tf32(v.x), f2tf32(v.y), f2tf32(v.z), f2tf32(v.w));
        reinterpret_cast<uint4*>(g_Wt)[i] = u;
    }
}

__device__ __forceinline__ uint32_t smem_u32(const void* p) {
    uint32_t a;
    asm("{ .reg .u64 t; cvta.to.shared.u64 t, %1; cvt.u32.u64 %0, t; }" : "=r"(a) : "l"(p));
    return a;
}

__device__ __forceinline__ void cp16(uint32_t dst, const void* src) {
    asm volatile("cp.async.cg.shared.global [%0], [%1], 16;" :: "r"(dst), "l"(src));
}

__device__ __forceinline__ void ldsm_x4(uint32_t* r, uint32_t addr) {
    asm volatile("ldmatrix.sync.aligned.m8n8.x4.shared.b16 {%0,%1,%2,%3}, [%4];"
                 : "=r"(r[0]), "=r"(r[1]), "=r"(r[2]), "=r"(r[3]) : "r"(addr));
}

__device__ __forceinline__ void mma_tf32(float* acc, const uint32_t* a, const uint32_t* b) {
    asm volatile(
        "mma.sync.aligned.m16n8k8.row.col.f32.tf32.tf32.f32 "
        "{%0,%1,%2,%3}, {%4,%5,%6,%7}, {%8,%9}, {%0,%1,%2,%3};\n"
        : "+f"(acc[0]), "+f"(acc[1]), "+f"(acc[2]), "+f"(acc[3])
        : "r"(a[0]), "r"(a[1]), "r"(a[2]), "r"(a[3]), "r"(b[0]), "r"(b[1]));
}

__global__ __launch_bounds__(NTHREADS, 2)
void dirnet_gemm_kernel(const float* __restrict__ x, const float* __restrict__ bias,
                        float* __restrict__ out) {
    extern __shared__ uint32_t sm[];
    const uint32_t smb = smem_u32(sm);

    const int o   = blockIdx.z;
    const int mt  = blockIdx.y;
    const int nt  = blockIdx.x;
    const int tid = threadIdx.x;
    const int lane = tid & 31;
    const int wid  = tid >> 5;          // 0..7
    const int g  = lane >> 2;           // 0..7
    const int t4 = lane & 3;            // 0..3
    const int wm = wid >> 2;            // 0..1 -> 64 rows
    const int wn = wid & 3;             // 0..3 -> 32 cols
    const int mBase = wm * 64;
    const int nBase = wn * 32;

    // ---- producer addressing: per thread 4 float4 of A (LDG->cvt->STS), 4 cp16 of B ----
    const int rowb = tid >> 3;          // 0..31
    const int c4   = tid & 7;
    int aOff[4];
    #pragma unroll
    for (int it = 0; it < 4; it++) {
        int row = rowb + 32 * it;
        int m   = mt * BM + row;
        int kb  = m / J_;
        int j   = m - kb * J_;
        aOff[it] = ((kb * O_ + o) * J_ + j) * DIM + c4 * 4;
    }
    const int bOff0 = o * (DIM * DIM) + (nt * BN + rowb) * DIM + c4 * 4;   // + it*32*DIM
    const uint32_t tA0 = (uint32_t)(rowb * ST + c4 * 4);                   // + it*32*ST (u32)
    const uint32_t tB0 = (uint32_t)((SA_U32 + rowb * ST + c4 * 4) * 4);    // + it*32*ST*4 (bytes)

    // ---- ldmatrix per-thread source addresses (byte offsets within a stage) ----
    const int r8  = lane & 7;
    const int seg = lane >> 3;          // 0..3
    uint32_t ofA[4], ofB[2];
    #pragma unroll
    for (int mf = 0; mf < 4; mf++)
        ofA[mf] = (uint32_t)(((mBase + mf * 16 + (seg & 1) * 8 + r8) * ST + (seg >> 1) * 4) * 4);
    #pragma unroll
    for (int p = 0; p < 2; p++)
        ofB[p] = (uint32_t)((SA_U32 + (nBase + (2 * p + (seg >> 1)) * 8 + r8) * ST
                             + (seg & 1) * 4) * 4);

    // ---- prologue: stages 0,1 in flight; A(2) prefetched to regs ----
    float4 ra[4];
    #pragma unroll
    for (int s = 0; s < 2; s++) {
        uint32_t base = smb + s * STG_U32 * 4;
        #pragma unroll
        for (int it = 0; it < 4; it++) {
            cp16(base + tB0 + (uint32_t)(it * 32 * ST * 4),
                 g_Wt + bOff0 + it * 32 * DIM + s * BK);
            float4 v = *reinterpret_cast<const float4*>(x + aOff[it] + s * BK);
            uint4 u = make_uint4(f2tf32(v.x), f2tf32(v.y), f2tf32(v.z), f2tf32(v.w));
            *reinterpret_cast<uint4*>(&sm[s * STG_U32 + tA0 + it * 32 * ST]) = u;
        }
        asm volatile("cp.async.commit_group;" ::: "memory");
    }
    #pragma unroll
    for (int it = 0; it < 4; it++)
        ra[it] = *reinterpret_cast<const float4*>(x + aOff[it] + 2 * BK);

    float acc[4][4][4];
    #pragma unroll
    for (int a = 0; a < 4; a++)
        #pragma unroll
        for (int b = 0; b < 4; b++)
            #pragma unroll
            for (int c = 0; c < 4; c++) acc[a][b][c] = 0.f;

    for (int kt = 0; kt < NKT; kt++) {
        const int cur = kt % STAGES;
        asm volatile("cp.async.wait_group 1;" ::: "memory");
        __syncthreads();

        const uint32_t sbase = smb + cur * STG_U32 * 4;

        // ---- kstep 0 first: tensor pipe starts immediately after the barrier ----
        {
            uint32_t af[4][4], bf[2][4];
            #pragma unroll
            for (int mf = 0; mf < 4; mf++) ldsm_x4(af[mf], sbase + ofA[mf]);
            #pragma unroll
            for (int p = 0; p < 2; p++)   ldsm_x4(bf[p], sbase + ofB[p]);
            #pragma unroll
            for (int mf = 0; mf < 4; mf++)
                #pragma unroll
                for (int nf = 0; nf < 4; nf++)
                    mma_tf32(acc[mf][nf], af[mf], &bf[nf >> 1][(nf & 1) * 2]);
        }

        // ---- producer for stage kt+2, overlapped with ksteps 1-3 ----
        if (kt + 2 < NKT) {
            const int nxt = (kt + 2) % STAGES;
            uint32_t base = smb + nxt * STG_U32 * 4;
            #pragma unroll
            for (int it = 0; it < 4; it++) {
                cp16(base + tB0 + (uint32_t)(it * 32 * ST * 4),
                     g_Wt + bOff0 + it * 32 * DIM + (kt + 2) * BK);
                uint4 u = make_uint4(f2tf32(ra[it].x), f2tf32(ra[it].y),
                                     f2tf32(ra[it].z), f2tf32(ra[it].w));
                *reinterpret_cast<uint4*>(&sm[nxt * STG_U32 + tA0 + it * 32 * ST]) = u;
            }
        }
        asm volatile("cp.async.commit_group;" ::: "memory");
        if (kt + 3 < NKT) {
            #pragma unroll
            for (int it = 0; it < 4; it++)
                ra[it] = *reinterpret_cast<const float4*>(x + aOff[it] + (kt + 3) * BK);
        }

        // ---- ksteps 1-3 ----
        #pragma unroll
        for (int ks = 1; ks < 4; ks++) {
            const uint32_t kadd = (uint32_t)(ks * 32);
            uint32_t af[4][4], bf[2][4];
            #pragma unroll
            for (int mf = 0; mf < 4; mf++) ldsm_x4(af[mf], sbase + ofA[mf] + kadd);
            #pragma unroll
            for (int p = 0; p < 2; p++)   ldsm_x4(bf[p], sbase + ofB[p] + kadd);
            #pragma unroll
            for (int mf = 0; mf < 4; mf++)
                #pragma unroll
                for (int nf = 0; nf < 4; nf++)
                    mma_tf32(acc[mf][nf], af[mf], &bf[nf >> 1][(nf & 1) * 2]);
        }
    }

    // ---- epilogue ----
    const float* bRow = bias + o * DIM;
    #pragma unroll
    for (int mf = 0; mf < 4; mf++) {
        #pragma unroll
        for (int half = 0; half < 2; half++) {
            int mloc = mBase + mf * 16 + g + half * 8;
            int m  = mt * BM + mloc;
            int kb = m / J_;
            int j  = m - kb * J_;
            int rowOff = ((kb * O_ + o) * J_ + j) * DIM;
            int selv = g_sel[j];
            #pragma unroll
            for (int nf = 0; nf < 4; nf++) {
                int n = nt * BN + nBase + nf * 8 + t4 * 2;
                float v0, v1;
                if (selv) {
                    v0 = acc[mf][nf][half * 2 + 0] * SCALE_F + bRow[n];
                    v1 = acc[mf][nf][half * 2 + 1] * SCALE_F + bRow[n + 1];
                } else {
                    v0 = x[rowOff + n];
                    v1 = x[rowOff + n + 1];
                }
                *reinterpret_cast<float2*>(out + rowOff + n) = make_float2(v0, v1);
            }
        }
    }
}

extern "C" void kernel_launch(void* const* d_in, const int* in_sizes, int n_in,
                              void* d_out, int out_size) {
    const float* x   = (const float*)d_in[0];
    const float* W   = (const float*)d_in[1];
    const float* b   = (const float*)d_in[2];
    const int*   idx = (const int*)d_in[3];
    float* out = (float*)d_out;

    prep_kernel<<<1024, 256>>>(W, idx, in_sizes[3]);

    cudaFuncSetAttribute(dirnet_gemm_kernel,
                         cudaFuncAttributeMaxDynamicSharedMemorySize, SMEM_BYTES);

    dim3 grid(DIM / BN, M_TOTAL / BM, O_);
    dirnet_gemm_kernel<<<grid, NTHREADS, SMEM_BYTES>>>(x, b, out);
}

// round 12
// speedup vs baseline: 1.4803x; 1.4803x over previous
#include <cuda_runtime.h>
#include <cuda_fp16.h>
#include <cstdint>

// x (256,18,18,512) f32, W (18,512,512) f32, b (18,512) f32, idx (18) i32
#define KB_   256
#define O_    18
#define J_    18
#define DIM   512
#define M_TOTAL (KB_ * J_)        // 4608
#define BM    128
#define BN    128
#define BKH   64                  // k elements per tile (fp16)
#define ST2   72                  // smem row stride in halves: 64 + 8 pad
#define NKT   (DIM / BKH)         // 8
#define STAGES 3
#define NTHREADS 256
#define SCALE_F 0.044194173824159216f

#define SA_H  (BM * ST2)                    // 9216 halves
#define STG_H (2 * SA_H)                    // 18432 halves = 36864 B
#define SMEM_BYTES (STAGES * STG_H * 2)     // 110592

#define X_ELEMS (KB_ * O_ * J_ * DIM)       // 42467328
#define W_ELEMS (O_ * DIM * DIM)            // 4718592

__device__ int g_sel[J_];
__device__ uint4 g_xh4[X_ELEMS / 8];        // x as fp16 (8 halves per uint4)
__device__ uint4 g_Wh4[W_ELEMS / 8];        // W as fp16

__global__ void prep_kernel(const float* __restrict__ x, const float* __restrict__ W,
                            const int* __restrict__ idx, int n) {
    if (blockIdx.x == 0 && threadIdx.x < 32) {
        int t = threadIdx.x;
        if (t < J_) g_sel[t] = 0;
        __syncwarp();
        if (t < n) {
            int v = idx[t];
            if (v >= 0 && v < J_) g_sel[v] = 1;
        }
    }
    const int nx = X_ELEMS / 8;
    for (int i = blockIdx.x * blockDim.x + threadIdx.x; i < nx;
         i += gridDim.x * blockDim.x) {
        float4 a = reinterpret_cast<const float4*>(x)[2 * i];
        float4 b = reinterpret_cast<const float4*>(x)[2 * i + 1];
        __half2 h0 = __floats2half2_rn(a.x, a.y);
        __half2 h1 = __floats2half2_rn(a.z, a.w);
        __half2 h2 = __floats2half2_rn(b.x, b.y);
        __half2 h3 = __floats2half2_rn(b.z, b.w);
        uint4 u;
        u.x = *reinterpret_cast<uint32_t*>(&h0);
        u.y = *reinterpret_cast<uint32_t*>(&h1);
        u.z = *reinterpret_cast<uint32_t*>(&h2);
        u.w = *reinterpret_cast<uint32_t*>(&h3);
        g_xh4[i] = u;
    }
    const int nw = W_ELEMS / 8;
    for (int i = blockIdx.x * blockDim.x + threadIdx.x; i < nw;
         i += gridDim.x * blockDim.x) {
        float4 a = reinterpret_cast<const float4*>(W)[2 * i];
        float4 b = reinterpret_cast<const float4*>(W)[2 * i + 1];
        __half2 h0 = __floats2half2_rn(a.x, a.y);
        __half2 h1 = __floats2half2_rn(a.z, a.w);
        __half2 h2 = __floats2half2_rn(b.x, b.y);
        __half2 h3 = __floats2half2_rn(b.z, b.w);
        uint4 u;
        u.x = *reinterpret_cast<uint32_t*>(&h0);
        u.y = *reinterpret_cast<uint32_t*>(&h1);
        u.z = *reinterpret_cast<uint32_t*>(&h2);
        u.w = *reinterpret_cast<uint32_t*>(&h3);
        g_Wh4[i] = u;
    }
}

__device__ __forceinline__ uint32_t smem_u32(const void* p) {
    uint32_t a;
    asm("{ .reg .u64 t; cvta.to.shared.u64 t, %1; cvt.u32.u64 %0, t; }" : "=r"(a) : "l"(p));
    return a;
}

__device__ __forceinline__ void cp16(uint32_t dst, const void* src) {
    asm volatile("cp.async.cg.shared.global [%0], [%1], 16;" :: "r"(dst), "l"(src));
}

__device__ __forceinline__ void ldsm_x4(uint32_t* r, uint32_t addr) {
    asm volatile("ldmatrix.sync.aligned.m8n8.x4.shared.b16 {%0,%1,%2,%3}, [%4];"
                 : "=r"(r[0]), "=r"(r[1]), "=r"(r[2]), "=r"(r[3]) : "r"(addr));
}

__device__ __forceinline__ void ldsm_x2(uint32_t* r, uint32_t addr) {
    asm volatile("ldmatrix.sync.aligned.m8n8.x2.shared.b16 {%0,%1}, [%2];"
                 : "=r"(r[0]), "=r"(r[1]) : "r"(addr));
}

__device__ __forceinline__ void mma_f16(float* acc, const uint32_t* a, const uint32_t* b) {
    asm volatile(
        "mma.sync.aligned.m16n8k16.row.col.f32.f16.f16.f32 "
        "{%0,%1,%2,%3}, {%4,%5,%6,%7}, {%8,%9}, {%0,%1,%2,%3};\n"
        : "+f"(acc[0]), "+f"(acc[1]), "+f"(acc[2]), "+f"(acc[3])
        : "r"(a[0]), "r"(a[1]), "r"(a[2]), "r"(a[3]), "r"(b[0]), "r"(b[1]));
}

__global__ __launch_bounds__(NTHREADS, 2)
void dirnet_gemm_kernel(const float* __restrict__ x, const float* __restrict__ bias,
                        float* __restrict__ out) {
    extern __shared__ __half smh[];
    const uint32_t smb = smem_u32(smh);
    const __half* xh = reinterpret_cast<const __half*>(g_xh4);
    const __half* wh = reinterpret_cast<const __half*>(g_Wh4);

    const int o   = blockIdx.z;
    const int mt  = blockIdx.y;
    const int nt  = blockIdx.x;
    const int tid = threadIdx.x;
    const int lane = tid & 31;
    const int wid  = tid >> 5;          // 0..7
    const int g  = lane >> 2;           // 0..7
    const int t4 = lane & 3;            // 0..3
    const int wm = wid >> 2;            // 0..1 -> 64 rows
    const int wn = wid & 3;             // 0..3 -> 32 cols
    const int mBase = wm * 64;
    const int nBase = wn * 32;

    // ---- producer: 4 A cp16 + 4 B cp16 per thread per ktile ----
    // f = tid + it*256 : row = f>>3 (0..127), c16 = f&7 (16B chunk = 8 halves)
    int aSrc[4], bSrc[4];               // element offsets (halves), + kt*BKH at use
    uint32_t tAOff[4], tBOff[4];        // byte offsets within a stage
    #pragma unroll
    for (int it = 0; it < 4; it++) {
        int f   = tid + it * 256;
        int row = f >> 3;
        int c16 = f & 7;
        int m   = mt * BM + row;
        int kb  = m / J_;
        int j   = m - kb * J_;
        aSrc[it]  = ((kb * O_ + o) * J_ + j) * DIM + c16 * 8;
        bSrc[it]  = o * (DIM * DIM) + (nt * BN + row) * DIM + c16 * 8;
        tAOff[it] = (uint32_t)((row * ST2 + c16 * 8) * 2);
        tBOff[it] = (uint32_t)((SA_H + row * ST2 + c16 * 8) * 2);
    }

    // ---- ldmatrix per-thread addresses (byte offsets within a stage) ----
    const int r8  = lane & 7;
    const int seg = lane >> 3;          // 0..3
    uint32_t ofA[4], ofB[2];
    #pragma unroll
    for (int mf = 0; mf < 4; mf++)
        ofA[mf] = (uint32_t)(((mBase + mf * 16 + (seg & 1) * 8 + r8) * ST2
                              + (seg >> 1) * 8) * 2);
    #pragma unroll
    for (int p = 0; p < 2; p++)
        ofB[p] = (uint32_t)((SA_H + (nBase + (2 * p + (seg >> 1)) * 8 + r8) * ST2
                             + (seg & 1) * 8) * 2);

    // ---- prologue: stages 0,1 in flight ----
    #pragma unroll
    for (int s = 0; s < 2; s++) {
        uint32_t base = smb + s * STG_H * 2;
        #pragma unroll
        for (int it = 0; it < 4; it++) {
            cp16(base + tAOff[it], xh + aSrc[it] + s * BKH);
            cp16(base + tBOff[it], wh + bSrc[it] + s * BKH);
        }
        asm volatile("cp.async.commit_group;" ::: "memory");
    }

    float acc[4][4][4];
    #pragma unroll
    for (int a = 0; a < 4; a++)
        #pragma unroll
        for (int b = 0; b < 4; b++)
            #pragma unroll
            for (int c = 0; c < 4; c++) acc[a][b][c] = 0.f;

    for (int kt = 0; kt < NKT; kt++) {
        const int cur = kt % STAGES;
        asm volatile("cp.async.wait_group 1;" ::: "memory");
        __syncthreads();

        const uint32_t sbase = smb + cur * STG_H * 2;

        // ---- kstep 0 first: tensor pipe starts immediately ----
        {
            uint32_t af[4][4], bf[2][4];
            #pragma unroll
            for (int mf = 0; mf < 4; mf++) ldsm_x4(af[mf], sbase + ofA[mf]);
            #pragma unroll
            for (int p = 0; p < 2; p++)   ldsm_x4(bf[p], sbase + ofB[p]);
            #pragma unroll
            for (int mf = 0; mf < 4; mf++)
                #pragma unroll
                for (int nf = 0; nf < 4; nf++)
                    mma_f16(acc[mf][nf], af[mf], &bf[nf >> 1][(nf & 1) * 2]);
        }

        // ---- producer for stage kt+2 (pure cp.async), overlapped with ksteps 1-3 ----
        if (kt + 2 < NKT) {
            const int nxt = (kt + 2) % STAGES;
            uint32_t base = smb + nxt * STG_H * 2;
            #pragma unroll
            for (int it = 0; it < 4; it++) {
                cp16(base + tAOff[it], xh + aSrc[it] + (kt + 2) * BKH);
                cp16(base + tBOff[it], wh + bSrc[it] + (kt + 2) * BKH);
            }
        }
        asm volatile("cp.async.commit_group;" ::: "memory");

        // ---- ksteps 1-3 ----
        #pragma unroll
        for (int ks = 1; ks < 4; ks++) {
            const uint32_t kadd = (uint32_t)(ks * 32);   // 16 halves = 32 B per kstep
            uint32_t af[4][4], bf[2][4];
            #pragma unroll
            for (int mf = 0; mf < 4; mf++) ldsm_x4(af[mf], sbase + ofA[mf] + kadd);
            #pragma unroll
            for (int p = 0; p < 2; p++)   ldsm_x4(bf[p], sbase + ofB[p] + kadd);
            #pragma unroll
            for (int mf = 0; mf < 4; mf++)
                #pragma unroll
                for (int nf = 0; nf < 4; nf++)
                    mma_f16(acc[mf][nf], af[mf], &bf[nf >> 1][(nf & 1) * 2]);
        }
    }

    // ---- epilogue ----
    const float* bRow = bias + o * DIM;
    #pragma unroll
    for (int mf = 0; mf < 4; mf++) {
        #pragma unroll
        for (int half = 0; half < 2; half++) {
            int mloc = mBase + mf * 16 + g + half * 8;
            int m  = mt * BM + mloc;
            int kb = m / J_;
            int j  = m - kb * J_;
            int rowOff = ((kb * O_ + o) * J_ + j) * DIM;
            int selv = g_sel[j];
            #pragma unroll
            for (int nf = 0; nf < 4; nf++) {
                int n = nt * BN + nBase + nf * 8 + t4 * 2;
                float v0, v1;
                if (selv) {
                    v0 = acc[mf][nf][half * 2 + 0] * SCALE_F + bRow[n];
                    v1 = acc[mf][nf][half * 2 + 1] * SCALE_F + bRow[n + 1];
                } else {
                    v0 = x[rowOff + n];
                    v1 = x[rowOff + n + 1];
                }
                *reinterpret_cast<float2*>(out + rowOff + n) = make_float2(v0, v1);
            }
        }
    }
}

extern "C" void kernel_launch(void* const* d_in, const int* in_sizes, int n_in,
                              void* d_out, int out_size) {
    const float* x   = (const float*)d_in[0];
    const float* W   = (const float*)d_in[1];
    const float* b   = (const float*)d_in[2];
    const int*   idx = (const int*)d_in[3];
    float* out = (float*)d_out;

    prep_kernel<<<2048, 256>>>(x, W, idx, in_sizes[3]);

    cudaFuncSetAttribute(dirnet_gemm_kernel,
                         cudaFuncAttributeMaxDynamicSharedMemorySize, SMEM_BYTES);

    dim3 grid(DIM / BN, M_TOTAL / BM, O_);
    dirnet_gemm_kernel<<<grid, NTHREADS, SMEM_BYTES>>>(x, b, out);
}